// round 15
// baseline (speedup 1.0000x reference)
#include <cuda_runtime.h>

// ---------------- problem constants ----------------
#define BB      32
#define NN      64
#define FA      82
#define FP      102
#define HH      8
#define DKK     80
#define HID     256
#define HB      (HH*BB)        // 256
#define ROWS    (BB*NN)        // 2048
#define PAIRS   (BB*NN*NN)     // 131072
#define CATK    722
#define CATS    724            // padded row stride for concat matrix
#define TPAD    68             // transposed-A smem row stride (16B multiple)

// ---------------- f32x2 packed helpers (sm_103a FFMA2) ----------------
__device__ __forceinline__ unsigned long long pk2(float x) {
    unsigned long long d;
    asm("mov.b64 %0, {%1, %1};" : "=l"(d) : "r"(__float_as_uint(x)));
    return d;
}
__device__ __forceinline__ unsigned long long ffma2(unsigned long long a,
                                                    unsigned long long b,
                                                    unsigned long long c) {
    unsigned long long d;
    asm("fma.rn.f32x2 %0, %1, %2, %3;" : "=l"(d) : "l"(a), "l"(b), "l"(c));
    return d;
}
__device__ __forceinline__ float2 upk2(unsigned long long d) {
    unsigned lo, hi;
    asm("mov.b64 {%0, %1}, %2;" : "=r"(lo), "=r"(hi) : "l"(d));
    return make_float2(__uint_as_float(lo), __uint_as_float(hi));
}

// ---------------- device scratch (no allocations allowed) ----------------
__device__ float g_Pc[(size_t)PAIRS*DKK];     // compacted: (path@W1p)+b_attn_h
__device__ float g_Qc[(size_t)PAIRS*DKK];     // compacted: path@W2p
__device__ float g_atom0[(size_t)HB*NN*DKK];  // atom_h0 [h*B+b, n, d]
__device__ float g_atomh[(size_t)HB*NN*DKK];  // current atom_h
__device__ float g_u [(size_t)HB*NN*DKK];
__device__ float g_v [(size_t)HB*NN*DKK];
__device__ float g_ws[(size_t)HB*NN*DKK];
__device__ float g_w [(size_t)HB*NN*DKK];
__device__ float g_cat[(size_t)ROWS*CATS];    // [atom_input | merged heads]
__device__ int   g_cnt[ROWS];
__device__ int   g_start[ROWS+1];
__device__ int   g_jidx[ROWS*NN];

// ============================================================
// Kernel M: per-(b,i) active-j list via warp ballot.
// ============================================================
__global__ void __launch_bounds__(256) k_mask(const float* __restrict__ mask) {
    const int bi = blockIdx.x * 8 + (threadIdx.x >> 5);
    const int lane = threadIdx.x & 31;
    const float m0 = mask[(size_t)bi*NN + lane];
    const float m1 = mask[(size_t)bi*NN + 32 + lane];
    const unsigned b0 = __ballot_sync(0xffffffffu, m0 != 0.f);
    const unsigned b1 = __ballot_sync(0xffffffffu, m1 != 0.f);
    const unsigned lt = (1u << lane) - 1u;
    const int c0 = __popc(b0);
    if (m0 != 0.f) g_jidx[bi*NN + __popc(b0 & lt)] = lane;
    if (m1 != 0.f) g_jidx[bi*NN + c0 + __popc(b1 & lt)] = lane + 32;
    if (lane == 0) g_cnt[bi] = c0 + __popc(b1);
}

// ============================================================
// Kernel S: exclusive prefix sum of g_cnt[2048] -> g_start. One CTA.
// ============================================================
__global__ void __launch_bounds__(256) k_scan() {
    __shared__ int warp_sums[8];
    __shared__ int warp_off[8];
    const int tid = threadIdx.x;
    const int base = tid * 8;
    int v[8]; int tot = 0;
#pragma unroll
    for (int i = 0; i < 8; i++) { v[i] = g_cnt[base + i]; tot += v[i]; }
    const int lane = tid & 31, wid = tid >> 5;
    int x = tot;
#pragma unroll
    for (int o = 1; o < 32; o <<= 1) {
        int y = __shfl_up_sync(0xffffffffu, x, o);
        if (lane >= o) x += y;
    }
    if (lane == 31) warp_sums[wid] = x;
    __syncthreads();
    if (tid == 0) {
        int a = 0;
#pragma unroll
        for (int w = 0; w < 8; w++) { warp_off[w] = a; a += warp_sums[w]; }
        g_start[ROWS] = a;
    }
    __syncthreads();
    int a = x - tot + warp_off[wid];
#pragma unroll
    for (int i = 0; i < 8; i++) { g_start[base + i] = a; a += v[i]; }
}

// ============================================================
// Kernel A: atom_h0 = atom_input @ W_atom_i (init g_atomh, g_cat[:, :82])
// ============================================================
__global__ void __launch_bounds__(256) k_proj0(const float* __restrict__ atom,
                                               const float* __restrict__ Wai) {
    __shared__ float As[64*FA];
    __shared__ float Bs[FA*DKK];
    const int tid = threadIdx.x;
    const int r0 = blockIdx.x * 64;
    const int h  = blockIdx.y;
    const int c0 = h * DKK;

    for (int i = tid; i < 64*FA; i += 256) As[i] = atom[(size_t)r0*FA + i];
    for (int i = tid; i < FA*DKK; i += 256) {
        int k = i / DKK, c = i % DKK;
        Bs[i] = Wai[(size_t)k*(HH*DKK) + c0 + c];
    }
    __syncthreads();

    const int ty = tid >> 4, tx = tid & 15;
    float acc[4][5];
#pragma unroll
    for (int r = 0; r < 4; r++)
#pragma unroll
        for (int c = 0; c < 5; c++) acc[r][c] = 0.f;

    for (int k = 0; k < FA; k++) {
        float a[4], b[5];
#pragma unroll
        for (int r = 0; r < 4; r++) a[r] = As[(ty*4+r)*FA + k];
#pragma unroll
        for (int c = 0; c < 5; c++) b[c] = Bs[k*DKK + tx*5 + c];
#pragma unroll
        for (int r = 0; r < 4; r++)
#pragma unroll
            for (int c = 0; c < 5; c++) acc[r][c] += a[r]*b[c];
    }

#pragma unroll
    for (int r = 0; r < 4; r++) {
        int row = r0 + ty*4 + r;
#pragma unroll
        for (int c = 0; c < 5; c++) {
            int d = tx*5 + c;
            size_t o = ((size_t)h*ROWS + row)*DKK + d;
            g_atom0[o] = acc[r][c];
            g_atomh[o] = acc[r][c];
        }
    }
    if (blockIdx.y == 0) {
        for (int i = tid; i < 64*FA; i += 256)
            g_cat[(size_t)(r0 + i/FA)*CATS + (i % FA)] = As[i];
    }
}

// ============================================================
// Kernel B': masked path projection. 128 slots/CTA = two 64-slot A sub-tiles
// against ONE staged B tile (160 cols). Single wave (~260 live CTAs on
// 296 slots at 2 CTAs/SM). Inner loop: transposed-A + FFMA2 + k+1 prefetch.
// ============================================================
__global__ void __launch_bounds__(256, 2) k_pathprojm(const float* __restrict__ path,
                                                      const float* __restrict__ Wah,
                                                      const float* __restrict__ Wmh,
                                                      const float* __restrict__ bah) {
    const int T = g_start[ROWS];
    const int t00 = blockIdx.x * 128;
    if (t00 >= T) return;

    extern __shared__ float sm[];
    float* At = sm;               // [FP][TPAD] transposed A (64 rows used)
    float* Bs = sm + FP*TPAD;     // [FP][160]
    __shared__ int sPair[128];

    const int tid = threadIdx.x;

    for (int i = tid; i < FP*160; i += 256) {
        int k = i / 160, c = i % 160;
        Bs[i] = (c < DKK) ? Wah[(size_t)(160+k)*DKK + c]
                          : Wmh[(size_t)(160+k)*DKK + (c - DKK)];
    }
    if (tid < 128) {
        int t = t00 + tid; if (t >= T) t = T - 1;
        int lo = 0, hi = ROWS - 1;
        while (lo < hi) {
            int mid = (lo + hi + 1) >> 1;
            if (__ldg(&g_start[mid]) <= t) lo = mid; else hi = mid - 1;
        }
        int slot = t - __ldg(&g_start[lo]);
        sPair[tid] = lo*NN + g_jidx[lo*NN + slot];
    }
    __syncthreads();

    const int ty = tid >> 4, tx = tid & 15;   // 4 rows x 10 cols per thread

    for (int sub = 0; sub < 2; sub++) {
        const int t0 = t00 + sub*64;
        if (t0 >= T) break;                    // uniform across CTA

        // gather A rows transposed: 4 threads per row
        {
            const int row = tid >> 2, part = tid & 3;
            const float2* src =
                reinterpret_cast<const float2*>(path) + (size_t)sPair[sub*64 + row]*51;
            const int q0 = part*13;
            const int q1 = (part == 3) ? 51 : q0 + 13;
            for (int q = q0; q < q1; q++) {
                float2 v = src[q];
                At[(2*q)  *TPAD + row] = v.x;
                At[(2*q+1)*TPAD + row] = v.y;
            }
        }
        __syncthreads();

        unsigned long long acc[4][5];
#pragma unroll
        for (int r = 0; r < 4; r++)
#pragma unroll
            for (int c = 0; c < 5; c++) acc[r][c] = 0ull;

        // software pipeline: prefetch k+1 while computing k
        float4 a_cur = *reinterpret_cast<const float4*>(At + 0*TPAD + ty*4);
        unsigned long long b_cur[5];
        {
            const unsigned long long* bp =
                reinterpret_cast<const unsigned long long*>(Bs + 0*160 + tx*10);
#pragma unroll
            for (int c = 0; c < 5; c++) b_cur[c] = bp[c];
        }

#pragma unroll 2
        for (int k = 0; k < FP; k++) {
            const int kn = (k + 1 < FP) ? k + 1 : k;
            const float4 a_nxt = *reinterpret_cast<const float4*>(At + kn*TPAD + ty*4);
            unsigned long long b_nxt[5];
            const unsigned long long* bp =
                reinterpret_cast<const unsigned long long*>(Bs + kn*160 + tx*10);
#pragma unroll
            for (int c = 0; c < 5; c++) b_nxt[c] = bp[c];

            const unsigned long long a0 = pk2(a_cur.x), a1 = pk2(a_cur.y),
                                     a2 = pk2(a_cur.z), a3 = pk2(a_cur.w);
#pragma unroll
            for (int c = 0; c < 5; c++) {
                acc[0][c] = ffma2(a0, b_cur[c], acc[0][c]);
                acc[1][c] = ffma2(a1, b_cur[c], acc[1][c]);
                acc[2][c] = ffma2(a2, b_cur[c], acc[2][c]);
                acc[3][c] = ffma2(a3, b_cur[c], acc[3][c]);
            }
            a_cur = a_nxt;
#pragma unroll
            for (int c = 0; c < 5; c++) b_cur[c] = b_nxt[c];
        }

#pragma unroll
        for (int r = 0; r < 4; r++) {
            int t = t0 + ty*4 + r;
            if (t >= T) continue;
#pragma unroll
            for (int c = 0; c < 5; c++) {
                const int col = tx*10 + 2*c;   // chunk never straddles col 80
                const float2 v = upk2(acc[r][c]);
                if (col < DKK) {
                    g_Pc[(size_t)t*DKK + col]     = v.x + bah[col];
                    g_Pc[(size_t)t*DKK + col + 1] = v.y + bah[col + 1];
                } else {
                    g_Qc[(size_t)t*DKK + (col - DKK)]     = v.x;
                    g_Qc[(size_t)t*DKK + (col - DKK) + 1] = v.y;
                }
            }
        }
        __syncthreads();   // done reading At before next sub-tile overwrites it
    }
}

// ============================================================
// Kernel P: {u,v,ws,w} = g_atomh @ {W1a,W1b,W2a,W2b} picked by blockIdx.y.
// 128 rows/CTA = two 64-row sub-tiles against one staged B tile.
// Grid (128, 4) = 512 CTAs -> single wave at 4 CTAs/SM.
// ============================================================
__global__ void __launch_bounds__(256, 4) k_proj4(const float* __restrict__ Wah,
                                                  const float* __restrict__ Wmh) {
    extern __shared__ float sm[];
    float* At = sm;               // [DKK][TPAD] transposed A (64 rows used)
    float* Bs = sm + DKK*TPAD;    // [DKK][80]
    const int tid = threadIdx.x;
    const size_t r00 = (size_t)blockIdx.x * 128;
    const int y = blockIdx.y;     // 0:u(W1a) 1:v(W1b) 2:ws(W2a) 3:w(W2b)

    {
        const float* Wsrc = ((y < 2) ? Wah : Wmh) + (size_t)((y & 1) * 80) * DKK;
        for (int i = tid; i < DKK*80; i += 256) {
            int k = i / 80, c = i % 80;
            Bs[i] = Wsrc[(size_t)k*DKK + c];
        }
    }
    float* dst = (y == 0) ? g_u : (y == 1) ? g_v : (y == 2) ? g_ws : g_w;

    const int tx  = tid & 7;      // 10 cols
    const int tyr = tid >> 3;     // 2 rows
    __syncthreads();

    for (int sub = 0; sub < 2; sub++) {
        const size_t r0 = r00 + sub*64;
        {
            const int row = tid >> 2, part = tid & 3;
            const float2* src = reinterpret_cast<const float2*>(g_atomh + (r0 + row)*DKK);
            const int q0 = part*10;
#pragma unroll
            for (int q = q0; q < q0 + 10; q++) {
                float2 v = src[q];
                At[(2*q)  *TPAD + row] = v.x;
                At[(2*q+1)*TPAD + row] = v.y;
            }
        }
        __syncthreads();

        unsigned long long acc[2][5];
#pragma unroll
        for (int r = 0; r < 2; r++)
#pragma unroll
            for (int c = 0; c < 5; c++) acc[r][c] = 0ull;

#pragma unroll 2
        for (int k = 0; k < DKK; k++) {
            const float2 af = *reinterpret_cast<const float2*>(At + k*TPAD + tyr*2);
            const unsigned long long a0 = pk2(af.x), a1 = pk2(af.y);
            const unsigned long long* bp =
                reinterpret_cast<const unsigned long long*>(Bs + k*80 + tx*10);
            unsigned long long b[5];
#pragma unroll
            for (int c = 0; c < 5; c++) b[c] = bp[c];
#pragma unroll
            for (int c = 0; c < 5; c++) {
                acc[0][c] = ffma2(a0, b[c], acc[0][c]);
                acc[1][c] = ffma2(a1, b[c], acc[1][c]);
            }
        }

#pragma unroll
        for (int rr = 0; rr < 2; rr++) {
            const size_t row = r0 + tyr*2 + rr;
#pragma unroll
            for (int c = 0; c < 5; c++) {
                const int col = tx*10 + 2*c;
                const float2 v = upk2(acc[rr][c]);
                dst[row*DKK + col]     = v.x;
                dst[row*DKK + col + 1] = v.y;
            }
        }
        __syncthreads();
    }
}

// ============================================================
// Kernel C: message-passing layer over ACTIVE slots only. CTA=(b,i), warp=head.
// Both slot loops unrolled x4 (interleaved shuffle chains / MLP-12 loads).
// ============================================================
__global__ void __launch_bounds__(256) k_attn(const float* __restrict__ Wo,
                                              const float* __restrict__ bo,
                                              const float* __restrict__ bmsg,
                                              int mode) {
    __shared__ float sP[NN*DKK];
    __shared__ float sQ[NN*DKK];
    __shared__ float sSc[HH*NN];
    __shared__ float sPr[HH*NN];
    __shared__ int   sJ[NN];

    const int tid = threadIdx.x;
    const int bi = blockIdx.x;
    const int b = bi >> 6;
    const int cnt  = g_cnt[bi];
    const int base = g_start[bi];

    {
        const float4* ps = reinterpret_cast<const float4*>(g_Pc + (size_t)base*DKK);
        const float4* qs = reinterpret_cast<const float4*>(g_Qc + (size_t)base*DKK);
        float4* pd = reinterpret_cast<float4*>(sP);
        float4* qd = reinterpret_cast<float4*>(sQ);
        const int n4 = cnt * (DKK/4);
        for (int t = tid; t < n4; t += 256) { pd[t] = ps[t]; qd[t] = qs[t]; }
    }
    if (tid < cnt) sJ[tid] = g_jidx[bi*NN + tid];
    __syncthreads();

    const int h = tid >> 5, lane = tid & 31;
    const int hb = h*BB + b;
    const size_t base_i = ((size_t)hb*NN + (bi & 63))*DKK;

    const float* urow = g_u + base_i;
    const float u0 = urow[lane], u1 = urow[lane+32];
    const float u2 = (lane < 16) ? urow[64+lane] : 0.f;
    const float w0 = Wo[lane], w1 = Wo[lane+32];
    const float w2 = (lane < 16) ? Wo[64+lane] : 0.f;

    const float* V = g_v + (size_t)hb*NN*DKK;
    float* sc = sSc + h*NN;

    // ---- pass 1: scores, x4 unrolled (4 interleaved shuffle chains) ----
    int s = 0;
    for (; s + 3 < cnt; s += 4) {
        float sv[4];
#pragma unroll
        for (int r = 0; r < 4; r++) {
            const float* vr = V + (size_t)sJ[s+r]*DKK;
            float h0 = u0 + vr[lane]    + sP[(s+r)*DKK + lane];
            float h1 = u1 + vr[lane+32] + sP[(s+r)*DKK + 32 + lane];
            float h2 = 0.f;
            if (lane < 16) h2 = u2 + vr[64+lane] + sP[(s+r)*DKK + 64 + lane];
            h0 = h0 > 0.f ? h0 : 0.2f*h0;
            h1 = h1 > 0.f ? h1 : 0.2f*h1;
            h2 = h2 > 0.f ? h2 : 0.2f*h2;
            sv[r] = h0*w0 + h1*w1 + h2*w2;
        }
#pragma unroll
        for (int o = 16; o >= 1; o >>= 1) {
#pragma unroll
            for (int r = 0; r < 4; r++)
                sv[r] += __shfl_xor_sync(0xffffffffu, sv[r], o);
        }
        if (lane == 0) {
            sc[s] = sv[0]; sc[s+1] = sv[1]; sc[s+2] = sv[2]; sc[s+3] = sv[3];
        }
    }
    for (; s < cnt; s++) {
        const float* vr = V + (size_t)sJ[s]*DKK;
        float h0 = u0 + vr[lane]    + sP[s*DKK + lane];
        float h1 = u1 + vr[lane+32] + sP[s*DKK + 32 + lane];
        float h2 = 0.f;
        if (lane < 16) h2 = u2 + vr[64+lane] + sP[s*DKK + 64 + lane];
        h0 = h0 > 0.f ? h0 : 0.2f*h0;
        h1 = h1 > 0.f ? h1 : 0.2f*h1;
        h2 = h2 > 0.f ? h2 : 0.2f*h2;
        float sv = h0*w0 + h1*w1 + h2*w2;
#pragma unroll
        for (int o = 16; o >= 1; o >>= 1) sv += __shfl_xor_sync(0xffffffffu, sv, o);
        if (lane == 0) sc[s] = sv;
    }
    __syncwarp();

    // ---- masked softmax (masked scores are exactly 0) ----
    const float bov = bo[0];
    float s0 = (lane      < cnt) ? sc[lane]      + bov : -1e30f;
    float s1 = (lane + 32 < cnt) ? sc[lane + 32] + bov : -1e30f;
    float mx = fmaxf(s0, s1);
#pragma unroll
    for (int o = 16; o >= 1; o >>= 1) mx = fmaxf(mx, __shfl_xor_sync(0xffffffffu, mx, o));
    if (cnt < NN) mx = fmaxf(mx, 0.f);
    float e0 = (lane      < cnt) ? __expf(s0 - mx) : 0.f;
    float e1 = (lane + 32 < cnt) ? __expf(s1 - mx) : 0.f;
    float tot = e0 + e1;
#pragma unroll
    for (int o = 16; o >= 1; o >>= 1) tot += __shfl_xor_sync(0xffffffffu, tot, o);
    const float inv = 1.f / (tot + 1e-20f);
    sPr[h*NN + lane]      = e0 * inv;
    sPr[h*NN + lane + 32] = e1 * inv;
    const float S = tot * inv;
    __syncwarp();

    // ---- pass 2: weighted message accumulation, x4 unrolled ----
    const float* W_ = g_w + (size_t)hb*NN*DKK;
    const float* pr = sPr + h*NN;
    float a0 = 0.f, a1 = 0.f, a2 = 0.f;
    s = 0;
    for (; s + 3 < cnt; s += 4) {
#pragma unroll
        for (int r = 0; r < 4; r++) {
            const float p = pr[s+r];
            const float* wr = W_ + (size_t)sJ[s+r]*DKK;
            a0 += p * (wr[lane]    + sQ[(s+r)*DKK + lane]);
            a1 += p * (wr[lane+32] + sQ[(s+r)*DKK + 32 + lane]);
            if (lane < 16) a2 += p * (wr[64+lane] + sQ[(s+r)*DKK + 64 + lane]);
        }
    }
    for (; s < cnt; s++) {
        const float p = pr[s];
        const float* wr = W_ + (size_t)sJ[s]*DKK;
        a0 += p * (wr[lane]    + sQ[s*DKK + lane]);
        a1 += p * (wr[lane+32] + sQ[s*DKK + 32 + lane]);
        if (lane < 16) a2 += p * (wr[64+lane] + sQ[s*DKK + 64 + lane]);
    }

    const float* wsr = g_ws   + base_i;
    const float* a0r = g_atom0 + base_i;
    float n0 = fmaxf(S*wsr[lane]    + a0 + bmsg[lane]    + a0r[lane],    0.f);
    float n1 = fmaxf(S*wsr[lane+32] + a1 + bmsg[lane+32] + a0r[lane+32], 0.f);
    float n2 = 0.f;
    if (lane < 16) n2 = fmaxf(S*wsr[64+lane] + a2 + bmsg[64+lane] + a0r[64+lane], 0.f);

    if (mode == 0) {
        float* o = g_atomh + base_i;
        o[lane] = n0; o[lane+32] = n1; if (lane < 16) o[64+lane] = n2;
    } else {
        float* o = g_cat + (size_t)bi*CATS + FA + h*DKK;
        o[lane] = n0; o[lane+32] = n1; if (lane < 16) o[64+lane] = n2;
    }
}

// ============================================================
// Kernel E: out = relu(g_cat[2048,722] @ W_atom_o[722,256] + b)
// Transposed-A smem + FFMA2 + global->reg->smem chunk pipeline.
// ============================================================
__global__ void __launch_bounds__(256) k_final(const float* __restrict__ Wao,
                                               const float* __restrict__ bao,
                                               float* __restrict__ out) {
    __shared__ float At[64*TPAD];   // transposed A chunk [k][r]
    __shared__ float Bs[64*64];
    const int tid = threadIdx.x;
    const int r0 = blockIdx.x * 64;
    const int c0 = blockIdx.y * 64;
    const int ty = tid >> 4, tx = tid & 15;
    const int NCH = (CATK + 63) / 64;   // 12 chunks

    unsigned long long acc[4][2];
#pragma unroll
    for (int r = 0; r < 4; r++) { acc[r][0] = 0ull; acc[r][1] = 0ull; }

    float aReg[16], bReg[16];
    // prologue: load chunk 0 into registers
    {
        const int kc = (CATK < 64) ? CATK : 64;
#pragma unroll
        for (int i = 0; i < 16; i++) {
            const int t = tid + i*256;
            const int r = t >> 6, k = t & 63;
            aReg[i] = (k < kc) ? g_cat[(size_t)(r0 + r)*CATS + k] : 0.f;
        }
#pragma unroll
        for (int i = 0; i < 16; i++) {
            const int t = tid + i*256;
            const int k = t >> 6, c = t & 63;
            bReg[i] = (k < kc) ? Wao[(size_t)k*HID + c0 + c] : 0.f;
        }
    }

    for (int ch = 0; ch < NCH; ch++) {
        __syncthreads();   // previous compute done -> safe to overwrite smem
#pragma unroll
        for (int i = 0; i < 16; i++) {
            const int t = tid + i*256;
            const int r = t >> 6, k = t & 63;
            At[k*TPAD + r] = aReg[i];
        }
#pragma unroll
        for (int i = 0; i < 16; i++) {
            const int t = tid + i*256;
            Bs[t] = bReg[i];
        }
        __syncthreads();

        // issue next chunk's global loads (overlap with compute below)
        if (ch + 1 < NCH) {
            const int k0 = (ch + 1) * 64;
            const int kc = (CATK - k0 < 64) ? (CATK - k0) : 64;
#pragma unroll
            for (int i = 0; i < 16; i++) {
                const int t = tid + i*256;
                const int r = t >> 6, k = t & 63;
                aReg[i] = (k < kc) ? g_cat[(size_t)(r0 + r)*CATS + k0 + k] : 0.f;
            }
#pragma unroll
            for (int i = 0; i < 16; i++) {
                const int t = tid + i*256;
                const int k = t >> 6, c = t & 63;
                bReg[i] = (k < kc) ? Wao[(size_t)(k0 + k)*HID + c0 + c] : 0.f;
            }
        }

        // compute current chunk from smem
#pragma unroll 8
        for (int k = 0; k < 64; k++) {
            const float4 av = *reinterpret_cast<const float4*>(At + k*TPAD + ty*4);
            const unsigned long long* bp =
                reinterpret_cast<const unsigned long long*>(Bs + k*64 + tx*4);
            const unsigned long long b01 = bp[0], b23 = bp[1];
            const unsigned long long a0 = pk2(av.x), a1 = pk2(av.y),
                                     a2 = pk2(av.z), a3 = pk2(av.w);
            acc[0][0] = ffma2(a0, b01, acc[0][0]); acc[0][1] = ffma2(a0, b23, acc[0][1]);
            acc[1][0] = ffma2(a1, b01, acc[1][0]); acc[1][1] = ffma2(a1, b23, acc[1][1]);
            acc[2][0] = ffma2(a2, b01, acc[2][0]); acc[2][1] = ffma2(a2, b23, acc[2][1]);
            acc[3][0] = ffma2(a3, b01, acc[3][0]); acc[3][1] = ffma2(a3, b23, acc[3][1]);
        }
    }

#pragma unroll
    for (int r = 0; r < 4; r++) {
        int row = r0 + ty*4 + r;
        const float2 v01 = upk2(acc[r][0]);
        const float2 v23 = upk2(acc[r][1]);
        const int col = c0 + tx*4;
        out[(size_t)row*HID + col    ] = fmaxf(v01.x + bao[col    ], 0.f);
        out[(size_t)row*HID + col + 1] = fmaxf(v01.y + bao[col + 1], 0.f);
        out[(size_t)row*HID + col + 2] = fmaxf(v23.x + bao[col + 2], 0.f);
        out[(size_t)row*HID + col + 3] = fmaxf(v23.y + bao[col + 3], 0.f);
    }
}

// ============================================================
extern "C" void kernel_launch(void* const* d_in, const int* in_sizes, int n_in,
                              void* d_out, int out_size) {
    const float* atom = (const float*)d_in[0];
    const float* path = (const float*)d_in[1];
    const float* mask = (const float*)d_in[2];
    const float* Wai  = (const float*)d_in[3];
    const float* Wah  = (const float*)d_in[4];
    const float* bah  = (const float*)d_in[5];
    const float* Wo   = (const float*)d_in[6];
    const float* bo   = (const float*)d_in[7];
    const float* Wmh  = (const float*)d_in[8];
    const float* bmh  = (const float*)d_in[9];
    const float* Wao  = (const float*)d_in[10];
    const float* bao  = (const float*)d_in[11];
    float* out = (float*)d_out;

    const int SMEM_B = (FP*TPAD  + FP*160) * 4;   //  93,024 B -> 2 CTAs/SM
    const int SMEM_P = (DKK*TPAD + DKK*80) * 4;   //  47,360 B -> 4 CTAs/SM
    cudaFuncSetAttribute(k_pathprojm, cudaFuncAttributeMaxDynamicSharedMemorySize, SMEM_B);
    cudaFuncSetAttribute(k_proj4,     cudaFuncAttributeMaxDynamicSharedMemorySize, SMEM_P);

    k_mask     <<<ROWS/8,       256>>>(mask);
    k_scan     <<<1,            256>>>();
    k_proj0    <<<dim3(32, 8),  256>>>(atom, Wai);
    k_pathprojm<<<PAIRS/128,    256, SMEM_B>>>(path, Wah, Wmh, bah);
    k_proj4    <<<dim3(128, 4), 256, SMEM_P>>>(Wah, Wmh);    // layer 1 projections
    k_attn     <<<ROWS,         256>>>(Wo, bo, bmh, 0);      // layer 1 -> g_atomh
    k_proj4    <<<dim3(128, 4), 256, SMEM_P>>>(Wah, Wmh);    // layer 2 projections
    k_attn     <<<ROWS,         256>>>(Wo, bo, bmh, 1);      // layer 2 -> g_cat
    k_final    <<<dim3(32, 4),  256>>>(Wao, bao, out);
}

// round 16
// speedup vs baseline: 1.0006x; 1.0006x over previous
#include <cuda_runtime.h>

// ---------------- problem constants ----------------
#define BB      32
#define NN      64
#define FA      82
#define FP      102
#define HH      8
#define DKK     80
#define HID     256
#define HB      (HH*BB)        // 256
#define ROWS    (BB*NN)        // 2048
#define PAIRS   (BB*NN*NN)     // 131072
#define CATK    722
#define CATS    724            // padded row stride for concat matrix
#define TPAD    68             // transposed-A smem row stride (16B multiple)

// ---------------- f32x2 packed helpers (sm_103a FFMA2) ----------------
__device__ __forceinline__ unsigned long long pk2(float x) {
    unsigned long long d;
    asm("mov.b64 %0, {%1, %1};" : "=l"(d) : "r"(__float_as_uint(x)));
    return d;
}
__device__ __forceinline__ unsigned long long ffma2(unsigned long long a,
                                                    unsigned long long b,
                                                    unsigned long long c) {
    unsigned long long d;
    asm("fma.rn.f32x2 %0, %1, %2, %3;" : "=l"(d) : "l"(a), "l"(b), "l"(c));
    return d;
}
__device__ __forceinline__ float2 upk2(unsigned long long d) {
    unsigned lo, hi;
    asm("mov.b64 {%0, %1}, %2;" : "=r"(lo), "=r"(hi) : "l"(d));
    return make_float2(__uint_as_float(lo), __uint_as_float(hi));
}

// ---------------- device scratch (no allocations allowed) ----------------
__device__ float g_Pc[(size_t)PAIRS*DKK];     // compacted: (path@W1p)+b_attn_h
__device__ float g_Qc[(size_t)PAIRS*DKK];     // compacted: path@W2p
__device__ float g_atom0[(size_t)HB*NN*DKK];  // atom_h0 [h*B+b, n, d]
__device__ float g_atomh[(size_t)HB*NN*DKK];  // current atom_h
__device__ float g_u [(size_t)HB*NN*DKK];
__device__ float g_v [(size_t)HB*NN*DKK];
__device__ float g_ws[(size_t)HB*NN*DKK];
__device__ float g_w [(size_t)HB*NN*DKK];
__device__ float g_cat[(size_t)ROWS*CATS];    // [atom_input | merged heads]
__device__ int   g_cnt[ROWS];
__device__ int   g_start[ROWS+1];
__device__ int   g_jidx[ROWS*NN];

// ============================================================
// Kernel M: per-(b,i) active-j list via warp ballot.
// ============================================================
__global__ void __launch_bounds__(256) k_mask(const float* __restrict__ mask) {
    const int bi = blockIdx.x * 8 + (threadIdx.x >> 5);
    const int lane = threadIdx.x & 31;
    const float m0 = mask[(size_t)bi*NN + lane];
    const float m1 = mask[(size_t)bi*NN + 32 + lane];
    const unsigned b0 = __ballot_sync(0xffffffffu, m0 != 0.f);
    const unsigned b1 = __ballot_sync(0xffffffffu, m1 != 0.f);
    const unsigned lt = (1u << lane) - 1u;
    const int c0 = __popc(b0);
    if (m0 != 0.f) g_jidx[bi*NN + __popc(b0 & lt)] = lane;
    if (m1 != 0.f) g_jidx[bi*NN + c0 + __popc(b1 & lt)] = lane + 32;
    if (lane == 0) g_cnt[bi] = c0 + __popc(b1);
}

// ============================================================
// Kernel S: exclusive prefix sum of g_cnt[2048] -> g_start. One CTA.
// ============================================================
__global__ void __launch_bounds__(256) k_scan() {
    __shared__ int warp_sums[8];
    __shared__ int warp_off[8];
    const int tid = threadIdx.x;
    const int base = tid * 8;
    int v[8]; int tot = 0;
#pragma unroll
    for (int i = 0; i < 8; i++) { v[i] = g_cnt[base + i]; tot += v[i]; }
    const int lane = tid & 31, wid = tid >> 5;
    int x = tot;
#pragma unroll
    for (int o = 1; o < 32; o <<= 1) {
        int y = __shfl_up_sync(0xffffffffu, x, o);
        if (lane >= o) x += y;
    }
    if (lane == 31) warp_sums[wid] = x;
    __syncthreads();
    if (tid == 0) {
        int a = 0;
#pragma unroll
        for (int w = 0; w < 8; w++) { warp_off[w] = a; a += warp_sums[w]; }
        g_start[ROWS] = a;
    }
    __syncthreads();
    int a = x - tot + warp_off[wid];
#pragma unroll
    for (int i = 0; i < 8; i++) { g_start[base + i] = a; a += v[i]; }
}

// ============================================================
// Kernel A: atom_h0 = atom_input @ W_atom_i (init g_atomh, g_cat[:, :82])
// ============================================================
__global__ void __launch_bounds__(256) k_proj0(const float* __restrict__ atom,
                                               const float* __restrict__ Wai) {
    __shared__ float As[64*FA];
    __shared__ float Bs[FA*DKK];
    const int tid = threadIdx.x;
    const int r0 = blockIdx.x * 64;
    const int h  = blockIdx.y;
    const int c0 = h * DKK;

    for (int i = tid; i < 64*FA; i += 256) As[i] = atom[(size_t)r0*FA + i];
    for (int i = tid; i < FA*DKK; i += 256) {
        int k = i / DKK, c = i % DKK;
        Bs[i] = Wai[(size_t)k*(HH*DKK) + c0 + c];
    }
    __syncthreads();

    const int ty = tid >> 4, tx = tid & 15;
    float acc[4][5];
#pragma unroll
    for (int r = 0; r < 4; r++)
#pragma unroll
        for (int c = 0; c < 5; c++) acc[r][c] = 0.f;

    for (int k = 0; k < FA; k++) {
        float a[4], b[5];
#pragma unroll
        for (int r = 0; r < 4; r++) a[r] = As[(ty*4+r)*FA + k];
#pragma unroll
        for (int c = 0; c < 5; c++) b[c] = Bs[k*DKK + tx*5 + c];
#pragma unroll
        for (int r = 0; r < 4; r++)
#pragma unroll
            for (int c = 0; c < 5; c++) acc[r][c] += a[r]*b[c];
    }

#pragma unroll
    for (int r = 0; r < 4; r++) {
        int row = r0 + ty*4 + r;
#pragma unroll
        for (int c = 0; c < 5; c++) {
            int d = tx*5 + c;
            size_t o = ((size_t)h*ROWS + row)*DKK + d;
            g_atom0[o] = acc[r][c];
            g_atomh[o] = acc[r][c];
        }
    }
    if (blockIdx.y == 0) {
        for (int i = tid; i < 64*FA; i += 256)
            g_cat[(size_t)(r0 + i/FA)*CATS + (i % FA)] = As[i];
    }
}

// ============================================================
// Kernel B': masked path projection. 512 THREADS, 128 slots/CTA as two
// 64-slot subtiles vs one staged 160-col B tile. smem 93KB -> 2 CTAs/SM
// -> 32 warps/SM (8/SMSP) for latency hiding. Each thread: 2 rows x 10 cols.
// Per-output k-accumulation order unchanged -> bit-identical results.
// ============================================================
__global__ void __launch_bounds__(512, 2) k_pathprojm(const float* __restrict__ path,
                                                      const float* __restrict__ Wah,
                                                      const float* __restrict__ Wmh,
                                                      const float* __restrict__ bah) {
    const int T = g_start[ROWS];
    const int t00 = blockIdx.x * 128;
    if (t00 >= T) return;

    extern __shared__ float sm[];
    float* At = sm;               // [FP][TPAD] transposed A (64 rows used)
    float* Bs = sm + FP*TPAD;     // [FP][160]
    __shared__ int sPair[128];

    const int tid = threadIdx.x;

    for (int i = tid; i < FP*160; i += 512) {
        int k = i / 160, c = i % 160;
        Bs[i] = (c < DKK) ? Wah[(size_t)(160+k)*DKK + c]
                          : Wmh[(size_t)(160+k)*DKK + (c - DKK)];
    }
    if (tid < 128) {
        int t = t00 + tid; if (t >= T) t = T - 1;
        int lo = 0, hi = ROWS - 1;
        while (lo < hi) {
            int mid = (lo + hi + 1) >> 1;
            if (__ldg(&g_start[mid]) <= t) lo = mid; else hi = mid - 1;
        }
        int slot = t - __ldg(&g_start[lo]);
        sPair[tid] = lo*NN + g_jidx[lo*NN + slot];
    }
    __syncthreads();

    const int ty = tid >> 4;      // 0..31 -> 2 rows each
    const int tx = tid & 15;      // 10 cols each

    for (int sub = 0; sub < 2; sub++) {
        const int t0 = t00 + sub*64;
        if (t0 >= T) break;                    // uniform across CTA

        // gather A rows transposed: 8 threads per row (7/7/7/7/7/7/7/2 float2)
        {
            const int row = tid >> 3, part = tid & 7;
            const float2* src =
                reinterpret_cast<const float2*>(path) + (size_t)sPair[sub*64 + row]*51;
            const int q0 = part*7;
            const int q1 = (q0 + 7 < 51) ? q0 + 7 : 51;
            for (int q = q0; q < q1; q++) {
                float2 v = src[q];
                At[(2*q)  *TPAD + row] = v.x;
                At[(2*q+1)*TPAD + row] = v.y;
            }
        }
        __syncthreads();

        unsigned long long acc[2][5];
#pragma unroll
        for (int r = 0; r < 2; r++)
#pragma unroll
            for (int c = 0; c < 5; c++) acc[r][c] = 0ull;

#pragma unroll 2
        for (int k = 0; k < FP; k++) {
            const float2 af = *reinterpret_cast<const float2*>(At + k*TPAD + ty*2);
            const unsigned long long a0 = pk2(af.x), a1 = pk2(af.y);
            const unsigned long long* bp =
                reinterpret_cast<const unsigned long long*>(Bs + k*160 + tx*10);
            unsigned long long b[5];
#pragma unroll
            for (int c = 0; c < 5; c++) b[c] = bp[c];
#pragma unroll
            for (int c = 0; c < 5; c++) {
                acc[0][c] = ffma2(a0, b[c], acc[0][c]);
                acc[1][c] = ffma2(a1, b[c], acc[1][c]);
            }
        }

#pragma unroll
        for (int r = 0; r < 2; r++) {
            int t = t0 + ty*2 + r;
            if (t >= T) continue;
#pragma unroll
            for (int c = 0; c < 5; c++) {
                const int col = tx*10 + 2*c;   // chunk never straddles col 80
                const float2 v = upk2(acc[r][c]);
                if (col < DKK) {
                    g_Pc[(size_t)t*DKK + col]     = v.x + bah[col];
                    g_Pc[(size_t)t*DKK + col + 1] = v.y + bah[col + 1];
                } else {
                    g_Qc[(size_t)t*DKK + (col - DKK)]     = v.x;
                    g_Qc[(size_t)t*DKK + (col - DKK) + 1] = v.y;
                }
            }
        }
        __syncthreads();   // done reading At before next sub-tile overwrites it
    }
}

// ============================================================
// Kernel P: {u,v,ws,w} = g_atomh @ {W1a,W1b,W2a,W2b} picked by blockIdx.y.
// Round-14 version: 64 rows/CTA, grid (256,4), smem 47.4KB -> 4 CTAs/SM.
// ============================================================
__global__ void __launch_bounds__(256, 4) k_proj4(const float* __restrict__ Wah,
                                                  const float* __restrict__ Wmh) {
    extern __shared__ float sm[];
    float* At = sm;               // [DKK][TPAD] transposed A (64 rows used)
    float* Bs = sm + DKK*TPAD;    // [DKK][80]
    const int tid = threadIdx.x;
    const size_t r0 = (size_t)blockIdx.x * 64;
    const int y = blockIdx.y;     // 0:u(W1a) 1:v(W1b) 2:ws(W2a) 3:w(W2b)

    {
        const float* Wsrc = ((y < 2) ? Wah : Wmh) + (size_t)((y & 1) * 80) * DKK;
        for (int i = tid; i < DKK*80; i += 256) {
            int k = i / 80, c = i % 80;
            Bs[i] = Wsrc[(size_t)k*DKK + c];
        }
    }
    {
        const int row = tid >> 2, part = tid & 3;
        const float2* src = reinterpret_cast<const float2*>(g_atomh + (r0 + row)*DKK);
        const int q0 = part*10;
#pragma unroll
        for (int q = q0; q < q0 + 10; q++) {
            float2 v = src[q];
            At[(2*q)  *TPAD + row] = v.x;
            At[(2*q+1)*TPAD + row] = v.y;
        }
    }
    __syncthreads();

    const int tx  = tid & 7;      // 10 cols
    const int tyr = tid >> 3;     // 2 rows

    unsigned long long acc[2][5];
#pragma unroll
    for (int r = 0; r < 2; r++)
#pragma unroll
        for (int c = 0; c < 5; c++) acc[r][c] = 0ull;

#pragma unroll 2
    for (int k = 0; k < DKK; k++) {
        const float2 af = *reinterpret_cast<const float2*>(At + k*TPAD + tyr*2);
        const unsigned long long a0 = pk2(af.x), a1 = pk2(af.y);
        const unsigned long long* bp =
            reinterpret_cast<const unsigned long long*>(Bs + k*80 + tx*10);
        unsigned long long b[5];
#pragma unroll
        for (int c = 0; c < 5; c++) b[c] = bp[c];
#pragma unroll
        for (int c = 0; c < 5; c++) {
            acc[0][c] = ffma2(a0, b[c], acc[0][c]);
            acc[1][c] = ffma2(a1, b[c], acc[1][c]);
        }
    }

    float* dst = (y == 0) ? g_u : (y == 1) ? g_v : (y == 2) ? g_ws : g_w;
#pragma unroll
    for (int rr = 0; rr < 2; rr++) {
        const size_t row = r0 + tyr*2 + rr;
#pragma unroll
        for (int c = 0; c < 5; c++) {
            const int col = tx*10 + 2*c;
            const float2 v = upk2(acc[rr][c]);
            dst[row*DKK + col]     = v.x;
            dst[row*DKK + col + 1] = v.y;
        }
    }
}

// ============================================================
// Kernel C: message-passing layer over ACTIVE slots only. CTA=(b,i), warp=head.
// Both slot loops unrolled x4 (interleaved shuffle chains / MLP-12 loads).
// ============================================================
__global__ void __launch_bounds__(256) k_attn(const float* __restrict__ Wo,
                                              const float* __restrict__ bo,
                                              const float* __restrict__ bmsg,
                                              int mode) {
    __shared__ float sP[NN*DKK];
    __shared__ float sQ[NN*DKK];
    __shared__ float sSc[HH*NN];
    __shared__ float sPr[HH*NN];
    __shared__ int   sJ[NN];

    const int tid = threadIdx.x;
    const int bi = blockIdx.x;
    const int b = bi >> 6;
    const int cnt  = g_cnt[bi];
    const int base = g_start[bi];

    {
        const float4* ps = reinterpret_cast<const float4*>(g_Pc + (size_t)base*DKK);
        const float4* qs = reinterpret_cast<const float4*>(g_Qc + (size_t)base*DKK);
        float4* pd = reinterpret_cast<float4*>(sP);
        float4* qd = reinterpret_cast<float4*>(sQ);
        const int n4 = cnt * (DKK/4);
        for (int t = tid; t < n4; t += 256) { pd[t] = ps[t]; qd[t] = qs[t]; }
    }
    if (tid < cnt) sJ[tid] = g_jidx[bi*NN + tid];
    __syncthreads();

    const int h = tid >> 5, lane = tid & 31;
    const int hb = h*BB + b;
    const size_t base_i = ((size_t)hb*NN + (bi & 63))*DKK;

    const float* urow = g_u + base_i;
    const float u0 = urow[lane], u1 = urow[lane+32];
    const float u2 = (lane < 16) ? urow[64+lane] : 0.f;
    const float w0 = Wo[lane], w1 = Wo[lane+32];
    const float w2 = (lane < 16) ? Wo[64+lane] : 0.f;

    const float* V = g_v + (size_t)hb*NN*DKK;
    float* sc = sSc + h*NN;

    // ---- pass 1: scores, x4 unrolled (4 interleaved shuffle chains) ----
    int s = 0;
    for (; s + 3 < cnt; s += 4) {
        float sv[4];
#pragma unroll
        for (int r = 0; r < 4; r++) {
            const float* vr = V + (size_t)sJ[s+r]*DKK;
            float h0 = u0 + vr[lane]    + sP[(s+r)*DKK + lane];
            float h1 = u1 + vr[lane+32] + sP[(s+r)*DKK + 32 + lane];
            float h2 = 0.f;
            if (lane < 16) h2 = u2 + vr[64+lane] + sP[(s+r)*DKK + 64 + lane];
            h0 = h0 > 0.f ? h0 : 0.2f*h0;
            h1 = h1 > 0.f ? h1 : 0.2f*h1;
            h2 = h2 > 0.f ? h2 : 0.2f*h2;
            sv[r] = h0*w0 + h1*w1 + h2*w2;
        }
#pragma unroll
        for (int o = 16; o >= 1; o >>= 1) {
#pragma unroll
            for (int r = 0; r < 4; r++)
                sv[r] += __shfl_xor_sync(0xffffffffu, sv[r], o);
        }
        if (lane == 0) {
            sc[s] = sv[0]; sc[s+1] = sv[1]; sc[s+2] = sv[2]; sc[s+3] = sv[3];
        }
    }
    for (; s < cnt; s++) {
        const float* vr = V + (size_t)sJ[s]*DKK;
        float h0 = u0 + vr[lane]    + sP[s*DKK + lane];
        float h1 = u1 + vr[lane+32] + sP[s*DKK + 32 + lane];
        float h2 = 0.f;
        if (lane < 16) h2 = u2 + vr[64+lane] + sP[s*DKK + 64 + lane];
        h0 = h0 > 0.f ? h0 : 0.2f*h0;
        h1 = h1 > 0.f ? h1 : 0.2f*h1;
        h2 = h2 > 0.f ? h2 : 0.2f*h2;
        float sv = h0*w0 + h1*w1 + h2*w2;
#pragma unroll
        for (int o = 16; o >= 1; o >>= 1) sv += __shfl_xor_sync(0xffffffffu, sv, o);
        if (lane == 0) sc[s] = sv;
    }
    __syncwarp();

    // ---- masked softmax (masked scores are exactly 0) ----
    const float bov = bo[0];
    float s0 = (lane      < cnt) ? sc[lane]      + bov : -1e30f;
    float s1 = (lane + 32 < cnt) ? sc[lane + 32] + bov : -1e30f;
    float mx = fmaxf(s0, s1);
#pragma unroll
    for (int o = 16; o >= 1; o >>= 1) mx = fmaxf(mx, __shfl_xor_sync(0xffffffffu, mx, o));
    if (cnt < NN) mx = fmaxf(mx, 0.f);
    float e0 = (lane      < cnt) ? __expf(s0 - mx) : 0.f;
    float e1 = (lane + 32 < cnt) ? __expf(s1 - mx) : 0.f;
    float tot = e0 + e1;
#pragma unroll
    for (int o = 16; o >= 1; o >>= 1) tot += __shfl_xor_sync(0xffffffffu, tot, o);
    const float inv = 1.f / (tot + 1e-20f);
    sPr[h*NN + lane]      = e0 * inv;
    sPr[h*NN + lane + 32] = e1 * inv;
    const float S = tot * inv;
    __syncwarp();

    // ---- pass 2: weighted message accumulation, x4 unrolled ----
    const float* W_ = g_w + (size_t)hb*NN*DKK;
    const float* pr = sPr + h*NN;
    float a0 = 0.f, a1 = 0.f, a2 = 0.f;
    s = 0;
    for (; s + 3 < cnt; s += 4) {
#pragma unroll
        for (int r = 0; r < 4; r++) {
            const float p = pr[s+r];
            const float* wr = W_ + (size_t)sJ[s+r]*DKK;
            a0 += p * (wr[lane]    + sQ[(s+r)*DKK + lane]);
            a1 += p * (wr[lane+32] + sQ[(s+r)*DKK + 32 + lane]);
            if (lane < 16) a2 += p * (wr[64+lane] + sQ[(s+r)*DKK + 64 + lane]);
        }
    }
    for (; s < cnt; s++) {
        const float p = pr[s];
        const float* wr = W_ + (size_t)sJ[s]*DKK;
        a0 += p * (wr[lane]    + sQ[s*DKK + lane]);
        a1 += p * (wr[lane+32] + sQ[s*DKK + 32 + lane]);
        if (lane < 16) a2 += p * (wr[64+lane] + sQ[s*DKK + 64 + lane]);
    }

    const float* wsr = g_ws   + base_i;
    const float* a0r = g_atom0 + base_i;
    float n0 = fmaxf(S*wsr[lane]    + a0 + bmsg[lane]    + a0r[lane],    0.f);
    float n1 = fmaxf(S*wsr[lane+32] + a1 + bmsg[lane+32] + a0r[lane+32], 0.f);
    float n2 = 0.f;
    if (lane < 16) n2 = fmaxf(S*wsr[64+lane] + a2 + bmsg[64+lane] + a0r[64+lane], 0.f);

    if (mode == 0) {
        float* o = g_atomh + base_i;
        o[lane] = n0; o[lane+32] = n1; if (lane < 16) o[64+lane] = n2;
    } else {
        float* o = g_cat + (size_t)bi*CATS + FA + h*DKK;
        o[lane] = n0; o[lane+32] = n1; if (lane < 16) o[64+lane] = n2;
    }
}

// ============================================================
// Kernel E: out = relu(g_cat[2048,722] @ W_atom_o[722,256] + b)
// Transposed-A smem + FFMA2 + global->reg->smem chunk pipeline.
// ============================================================
__global__ void __launch_bounds__(256) k_final(const float* __restrict__ Wao,
                                               const float* __restrict__ bao,
                                               float* __restrict__ out) {
    __shared__ float At[64*TPAD];   // transposed A chunk [k][r]
    __shared__ float Bs[64*64];
    const int tid = threadIdx.x;
    const int r0 = blockIdx.x * 64;
    const int c0 = blockIdx.y * 64;
    const int ty = tid >> 4, tx = tid & 15;
    const int NCH = (CATK + 63) / 64;   // 12 chunks

    unsigned long long acc[4][2];
#pragma unroll
    for (int r = 0; r < 4; r++) { acc[r][0] = 0ull; acc[r][1] = 0ull; }

    float aReg[16], bReg[16];
    // prologue: load chunk 0 into registers
    {
        const int kc = (CATK < 64) ? CATK : 64;
#pragma unroll
        for (int i = 0; i < 16; i++) {
            const int t = tid + i*256;
            const int r = t >> 6, k = t & 63;
            aReg[i] = (k < kc) ? g_cat[(size_t)(r0 + r)*CATS + k] : 0.f;
        }
#pragma unroll
        for (int i = 0; i < 16; i++) {
            const int t = tid + i*256;
            const int k = t >> 6, c = t & 63;
            bReg[i] = (k < kc) ? Wao[(size_t)k*HID + c0 + c] : 0.f;
        }
    }

    for (int ch = 0; ch < NCH; ch++) {
        __syncthreads();   // previous compute done -> safe to overwrite smem
#pragma unroll
        for (int i = 0; i < 16; i++) {
            const int t = tid + i*256;
            const int r = t >> 6, k = t & 63;
            At[k*TPAD + r] = aReg[i];
        }
#pragma unroll
        for (int i = 0; i < 16; i++) {
            const int t = tid + i*256;
            Bs[t] = bReg[i];
        }
        __syncthreads();

        // issue next chunk's global loads (overlap with compute below)
        if (ch + 1 < NCH) {
            const int k0 = (ch + 1) * 64;
            const int kc = (CATK - k0 < 64) ? (CATK - k0) : 64;
#pragma unroll
            for (int i = 0; i < 16; i++) {
                const int t = tid + i*256;
                const int r = t >> 6, k = t & 63;
                aReg[i] = (k < kc) ? g_cat[(size_t)(r0 + r)*CATS + k0 + k] : 0.f;
            }
#pragma unroll
            for (int i = 0; i < 16; i++) {
                const int t = tid + i*256;
                const int k = t >> 6, c = t & 63;
                bReg[i] = (k < kc) ? Wao[(size_t)(k0 + k)*HID + c0 + c] : 0.f;
            }
        }

        // compute current chunk from smem
#pragma unroll 8
        for (int k = 0; k < 64; k++) {
            const float4 av = *reinterpret_cast<const float4*>(At + k*TPAD + ty*4);
            const unsigned long long* bp =
                reinterpret_cast<const unsigned long long*>(Bs + k*64 + tx*4);
            const unsigned long long b01 = bp[0], b23 = bp[1];
            const unsigned long long a0 = pk2(av.x), a1 = pk2(av.y),
                                     a2 = pk2(av.z), a3 = pk2(av.w);
            acc[0][0] = ffma2(a0, b01, acc[0][0]); acc[0][1] = ffma2(a0, b23, acc[0][1]);
            acc[1][0] = ffma2(a1, b01, acc[1][0]); acc[1][1] = ffma2(a1, b23, acc[1][1]);
            acc[2][0] = ffma2(a2, b01, acc[2][0]); acc[2][1] = ffma2(a2, b23, acc[2][1]);
            acc[3][0] = ffma2(a3, b01, acc[3][0]); acc[3][1] = ffma2(a3, b23, acc[3][1]);
        }
    }

#pragma unroll
    for (int r = 0; r < 4; r++) {
        int row = r0 + ty*4 + r;
        const float2 v01 = upk2(acc[r][0]);
        const float2 v23 = upk2(acc[r][1]);
        const int col = c0 + tx*4;
        out[(size_t)row*HID + col    ] = fmaxf(v01.x + bao[col    ], 0.f);
        out[(size_t)row*HID + col + 1] = fmaxf(v01.y + bao[col + 1], 0.f);
        out[(size_t)row*HID + col + 2] = fmaxf(v23.x + bao[col + 2], 0.f);
        out[(size_t)row*HID + col + 3] = fmaxf(v23.y + bao[col + 3], 0.f);
    }
}

// ============================================================
extern "C" void kernel_launch(void* const* d_in, const int* in_sizes, int n_in,
                              void* d_out, int out_size) {
    const float* atom = (const float*)d_in[0];
    const float* path = (const float*)d_in[1];
    const float* mask = (const float*)d_in[2];
    const float* Wai  = (const float*)d_in[3];
    const float* Wah  = (const float*)d_in[4];
    const float* bah  = (const float*)d_in[5];
    const float* Wo   = (const float*)d_in[6];
    const float* bo   = (const float*)d_in[7];
    const float* Wmh  = (const float*)d_in[8];
    const float* bmh  = (const float*)d_in[9];
    const float* Wao  = (const float*)d_in[10];
    const float* bao  = (const float*)d_in[11];
    float* out = (float*)d_out;

    const int SMEM_B = (FP*TPAD  + FP*160) * 4;   //  93,024 B -> 2 CTAs/SM
    const int SMEM_P = (DKK*TPAD + DKK*80) * 4;   //  47,360 B -> 4 CTAs/SM
    cudaFuncSetAttribute(k_pathprojm, cudaFuncAttributeMaxDynamicSharedMemorySize, SMEM_B);
    cudaFuncSetAttribute(k_proj4,     cudaFuncAttributeMaxDynamicSharedMemorySize, SMEM_P);

    k_mask     <<<ROWS/8,       256>>>(mask);
    k_scan     <<<1,            256>>>();
    k_proj0    <<<dim3(32, 8),  256>>>(atom, Wai);
    k_pathprojm<<<PAIRS/128,    512, SMEM_B>>>(path, Wah, Wmh, bah);
    k_proj4    <<<dim3(256, 4), 256, SMEM_P>>>(Wah, Wmh);    // layer 1 projections
    k_attn     <<<ROWS,         256>>>(Wo, bo, bmh, 0);      // layer 1 -> g_atomh
    k_proj4    <<<dim3(256, 4), 256, SMEM_P>>>(Wah, Wmh);    // layer 2 projections
    k_attn     <<<ROWS,         256>>>(Wo, bo, bmh, 1);      // layer 2 -> g_cat
    k_final    <<<dim3(32, 4),  256>>>(Wao, bao, out);
}